// round 8
// baseline (speedup 1.0000x reference)
#include <cuda_runtime.h>
#include <math.h>

#define BB 32
#define TT 4096
#define DD 256
#define KK 128         // frequency count = D/2
#define HH 512         // hidden = 2*D
#define TBLK 64        // tokens per block in main kernel
#define NTHR 256

// ---------------- scratch (global __device__, no allocation) ----------------
__device__ float2 g_tab[TT];        // (cos(2*pi*m/T), sin(2*pi*m/T))
__device__ float2 g_s0c0[BB * KK];  // (sin(phase0), cos(phase0))
__device__ float  g_base[BB * HH];  // mag @ w1[:128,:] + b1  (exact fp32 path)
__device__ unsigned g_w1t[KK * HH]; // tf32 bits of w1 rows 128..255
__device__ unsigned g_w2t[HH * DD]; // tf32 bits of w2

__device__ __forceinline__ unsigned f2tf32(float x) {
    unsigned r;
    asm("cvt.rna.tf32.f32 %0, %1;" : "=r"(r) : "f"(x));
    return r;
}

__device__ __forceinline__ void mma8(float* d,
                                     unsigned a0, unsigned a1, unsigned a2, unsigned a3,
                                     unsigned b0, unsigned b1) {
    asm volatile("mma.sync.aligned.m16n8k8.row.col.f32.tf32.tf32.f32 "
                 "{%0,%1,%2,%3}, {%4,%5,%6,%7}, {%8,%9}, {%0,%1,%2,%3};\n"
                 : "+f"(d[0]), "+f"(d[1]), "+f"(d[2]), "+f"(d[3])
                 : "r"(a0), "r"(a1), "r"(a2), "r"(a3), "r"(b0), "r"(b1));
}

// ---------------- kernel A: weights -> tf32 bits ----------------------------
__global__ void k_prep(const float* __restrict__ w1, const float* __restrict__ w2) {
    int i = blockIdx.x * blockDim.x + threadIdx.x;
    if (i < KK * HH) g_w1t[i] = f2tf32(w1[KK * HH + i]);   // rows 128..255
    if (i < HH * DD) g_w2t[i] = f2tf32(w2[i]);
}

// ---------------- kernel B: per-batch DFT + mag-fold (tab, dft, base) -------
// one block per batch b, 1024 threads
__global__ void __launch_bounds__(1024, 1)
k_all(const int* __restrict__ byte_ids,
      const float* __restrict__ freq_bands,
      const float* __restrict__ w1,
      const float* __restrict__ b1) {
    __shared__ float  sig[TT];     // 16 KB
    __shared__ float2 stab[TT];    // 32 KB
    __shared__ float  mg[KK];      // mag * freq_bands

    int b = blockIdx.x;
    int tid = threadIdx.x;
    int w = tid >> 5, lane = tid & 31;

    // trig table (4 entries/thread) + signal (4 entries/thread)
    #pragma unroll
    for (int q = 0; q < 4; ++q) {
        int m = tid + q * 1024;
        float s, c;
        sincospif((float)m * (1.0f / 2048.0f), &s, &c);
        stab[m] = make_float2(c, s);
        sig[m] = (float)byte_ids[b * TT + m] * (1.0f / 127.5f) - 1.0f;
    }
    __syncthreads();

    // publish g_tab once for k_main
    if (b == 0) {
        #pragma unroll
        for (int q = 0; q < 4; ++q) g_tab[tid + q * 1024] = stab[tid + q * 1024];
    }

    // DFT: warp w handles freqs f = q*32 + w, q = 0..3
    #pragma unroll 1
    for (int q = 0; q < 4; ++q) {
        int f = q * 32 + w;
        float re = 0.f, im = 0.f;
        #pragma unroll 4
        for (int t = lane; t < TT; t += 32) {
            int m = (f * t) & (TT - 1);
            float2 cs = stab[m];
            float s = sig[t];
            re += s * cs.x;
            im -= s * cs.y;
        }
        #pragma unroll
        for (int o = 16; o > 0; o >>= 1) {
            re += __shfl_xor_sync(0xffffffffu, re, o);
            im += __shfl_xor_sync(0xffffffffu, im, o);
        }
        if (lane == 0) {
            float mr = sqrtf(re * re + im * im);
            float s0, c0;
            if (mr > 0.f) { s0 = im / mr; c0 = re / mr; }
            else          { s0 = 0.f;    c0 = 1.f;    }
            mg[f] = mr * freq_bands[f];
            g_s0c0[b * KK + f] = make_float2(s0, c0);
        }
    }
    __syncthreads();

    // base[j] = b1[j] + sum_f mg[f] * w1[f][j]   (exact fp32), 512 threads
    if (tid < HH) {
        float acc = b1[tid];
        #pragma unroll 8
        for (int f = 0; f < KK; ++f) acc += mg[f] * w1[f * HH + tid];
        g_base[b * HH + tid] = acc;
    }
}

// ---------------- kernel C: fused feats->MMA1->LN->GELU->MMA2 ---------------
// smem word layout:
//   sa   [64][132]  unsigned tf32  (A of GEMM1; aliased as weight buf1 in GEMM2)
//   sG   [64][516]  float h  -> tf32 g  (epilogue/LN/A of GEMM2)
//   wb   [32][264]  unsigned tf32 weight staging (GEMM1: two 16-row bufs)
//   sbase[512] sgam[512] sbet[512]  float
#define SA_STR 132
#define SG_STR 516
#define WB_STR 264
#define OFF_SA   0
#define OFF_SG   (TBLK * SA_STR)                 // 8448
#define OFF_WB   (OFF_SG + TBLK * SG_STR)        // 41472
#define OFF_BASE (OFF_WB + 32 * WB_STR)          // 49920
#define OFF_GAM  (OFF_BASE + HH)
#define OFF_BET  (OFF_GAM + HH)
#define SM_WORDS (OFF_BET + HH)                  // 51456 words = 205824 B

__global__ void __launch_bounds__(NTHR, 1)
k_main(const float* __restrict__ b2,
       const float* __restrict__ gamma,
       const float* __restrict__ beta,
       float* __restrict__ out) {
    extern __shared__ float smem[];
    unsigned* sa   = (unsigned*)smem + OFF_SA;
    float*    sGf  = smem + OFF_SG;
    unsigned* sGu  = (unsigned*)smem + OFF_SG;
    unsigned* wb   = (unsigned*)smem + OFF_WB;
    unsigned* wbA  = (unsigned*)smem + OFF_SA;   // GEMM2 second weight buffer
    float*    sbase = smem + OFF_BASE;
    float*    sgam  = smem + OFF_GAM;
    float*    sbet  = smem + OFF_BET;

    int tid  = threadIdx.x;
    int lane = tid & 31, warp = tid >> 5;
    int b = blockIdx.y, t0 = blockIdx.x * TBLK;
    int mw = warp & 1, nw = warp >> 1;           // warp tile: rows mw*32, cols nw*64
    int gid = lane >> 2, t4 = lane & 3;

    // ---- feats: a[t][f] = sin(phase0 + 2*pi*f*(t0+t)/T), stored as tf32 ----
    for (int e = tid; e < TBLK * KK; e += NTHR) {
        int t = e >> 7, f = e & (KK - 1);
        int m = (f * (t0 + t)) & (TT - 1);
        float2 cs = g_tab[m];
        float2 sc = g_s0c0[b * KK + f];
        sa[t * SA_STR + f] = f2tf32(sc.x * cs.x + sc.y * cs.y);
    }
    for (int j = tid; j < HH; j += NTHR) {
        sbase[j] = g_base[b * HH + j];
        sgam[j]  = gamma[j];
        sbet[j]  = beta[j];
    }
    __syncthreads();

    // =========================== GEMM1 =====================================
    // h[64][512] = a[64][128] @ w1s[128][512] + base, two N-passes of 256
    {
        int srow = tid >> 4, scol = tid & 15;    // stage: 16 rows x 256 cols
        for (int p = 0; p < 2; ++p) {
            int n0 = p * 256;
            float acc[2][8][4];
            #pragma unroll
            for (int mt = 0; mt < 2; ++mt)
                #pragma unroll
                for (int nt = 0; nt < 8; ++nt)
                    #pragma unroll
                    for (int q = 0; q < 4; ++q) acc[mt][nt][q] = 0.f;

            uint4 rg[4];
            const uint4* wsrc = (const uint4*)g_w1t;
            // prologue: chunk 0 -> buf0
            #pragma unroll
            for (int i = 0; i < 4; ++i)
                rg[i] = wsrc[srow * (HH / 4) + (n0 >> 2) + scol + 16 * i];
            #pragma unroll
            for (int i = 0; i < 4; ++i)
                ((uint4*)wb)[srow * (WB_STR / 4) + scol + 16 * i] = rg[i];
            __syncthreads();

            for (int c = 0; c < 8; ++c) {
                int pb = c & 1;
                if (c < 7) {
                    #pragma unroll
                    for (int i = 0; i < 4; ++i)
                        rg[i] = wsrc[((c + 1) * 16 + srow) * (HH / 4) + (n0 >> 2) + scol + 16 * i];
                }
                const unsigned* wbc = wb + pb * 16 * WB_STR;
                #pragma unroll
                for (int kk = 0; kk < 16; kk += 8) {
                    int kg = c * 16 + kk;
                    unsigned a[2][4];
                    #pragma unroll
                    for (int mt = 0; mt < 2; ++mt) {
                        int rb = mw * 32 + mt * 16;
                        a[mt][0] = sa[(rb + gid)     * SA_STR + kg + t4];
                        a[mt][1] = sa[(rb + gid + 8) * SA_STR + kg + t4];
                        a[mt][2] = sa[(rb + gid)     * SA_STR + kg + t4 + 4];
                        a[mt][3] = sa[(rb + gid + 8) * SA_STR + kg + t4 + 4];
                    }
                    #pragma unroll
                    for (int nt = 0; nt < 8; ++nt) {
                        int nb = nw * 64 + nt * 8;
                        unsigned b0 = wbc[(kk + t4)     * WB_STR + nb + gid];
                        unsigned b1 = wbc[(kk + t4 + 4) * WB_STR + nb + gid];
                        mma8(acc[0][nt], a[0][0], a[0][1], a[0][2], a[0][3], b0, b1);
                        mma8(acc[1][nt], a[1][0], a[1][1], a[1][2], a[1][3], b0, b1);
                    }
                }
                if (c < 7) {
                    int pb2 = (c + 1) & 1;
                    #pragma unroll
                    for (int i = 0; i < 4; ++i)
                        ((uint4*)wb)[pb2 * 16 * (WB_STR / 4) + srow * (WB_STR / 4) + scol + 16 * i] = rg[i];
                }
                __syncthreads();
            }
            // epilogue: h = acc + base -> sG (fp32)
            #pragma unroll
            for (int mt = 0; mt < 2; ++mt) {
                int r0 = mw * 32 + mt * 16 + gid;
                #pragma unroll
                for (int nt = 0; nt < 8; ++nt) {
                    int col = n0 + nw * 64 + nt * 8 + 2 * t4;
                    float2 v0 = make_float2(acc[mt][nt][0] + sbase[col],
                                            acc[mt][nt][1] + sbase[col + 1]);
                    float2 v1 = make_float2(acc[mt][nt][2] + sbase[col],
                                            acc[mt][nt][3] + sbase[col + 1]);
                    *(float2*)(sGf + r0 * SG_STR + col)       = v0;
                    *(float2*)(sGf + (r0 + 8) * SG_STR + col) = v1;
                }
            }
        }
    }
    __syncthreads();

    // ---- LayerNorm + exact GELU (erf form); store back as tf32 bits ----
    {
        int row = tid >> 2, part = tid & 3;
        float* hr = sGf + row * SG_STR + part * 128;
        float sum = 0.f, sq = 0.f;
        #pragma unroll 4
        for (int i = 0; i < 128; ++i) { float v = hr[i]; sum += v; sq += v * v; }
        #pragma unroll
        for (int o = 1; o < 4; o <<= 1) {
            sum += __shfl_xor_sync(0xffffffffu, sum, o);
            sq  += __shfl_xor_sync(0xffffffffu, sq,  o);
        }
        float mu  = sum * (1.0f / 512.0f);
        float var = sq * (1.0f / 512.0f) - mu * mu;
        float rs  = rsqrtf(var + 1e-5f);
        unsigned* hu = (unsigned*)hr;
        #pragma unroll 4
        for (int i = 0; i < 128; ++i) {
            int j = part * 128 + i;
            float v = (hr[i] - mu) * rs * sgam[j] + sbet[j];
            float g = 0.5f * v * (1.0f + erff(v * 0.70710678118654752f));
            hu[i] = f2tf32(g);   // exact GELU via erf
        }
    }
    __syncthreads();

    // =========================== GEMM2 =====================================
    // out[64][256] = g[64][512] @ w2[512][256] + b2, single N-pass
    {
        float acc[2][8][4];
        #pragma unroll
        for (int mt = 0; mt < 2; ++mt)
            #pragma unroll
            for (int nt = 0; nt < 8; ++nt)
                #pragma unroll
                for (int q = 0; q < 4; ++q) acc[mt][nt][q] = 0.f;

        int srow = tid >> 3, scol = tid & 7;     // stage: 32 rows x 256 cols
        uint4 rg[8];
        const uint4* wsrc = (const uint4*)g_w2t;
        // prologue: chunk 0 -> wb (buf0)
        #pragma unroll
        for (int i = 0; i < 8; ++i)
            rg[i] = wsrc[srow * (DD / 4) + scol + 8 * i];
        #pragma unroll
        for (int i = 0; i < 8; ++i)
            ((uint4*)wb)[srow * (WB_STR / 4) + scol + 8 * i] = rg[i];
        __syncthreads();

        for (int c = 0; c < 16; ++c) {
            const unsigned* wbc = (c & 1) ? wbA : wb;
            if (c < 15) {
                #pragma unroll
                for (int i = 0; i < 8; ++i)
                    rg[i] = wsrc[((c + 1) * 32 + srow) * (DD / 4) + scol + 8 * i];
            }
            #pragma unroll
            for (int kk = 0; kk < 32; kk += 8) {
                int kg = c * 32 + kk;
                unsigned a[2][4];
                #pragma unroll
                for (int mt = 0; mt < 2; ++mt) {
                    int rb = mw * 32 + mt * 16;
                    a[mt][0] = sGu[(rb + gid)     * SG_STR + kg + t4];
                    a[mt][1] = sGu[(rb + gid + 8) * SG_STR + kg + t4];
                    a[mt][2] = sGu[(rb + gid)     * SG_STR + kg + t4 + 4];
                    a[mt][3] = sGu[(rb + gid + 8) * SG_STR + kg + t4 + 4];
                }
                #pragma unroll
                for (int nt = 0; nt < 8; ++nt) {
                    int nb = nw * 64 + nt * 8;
                    unsigned b0 = wbc[(kk + t4)     * WB_STR + nb + gid];
                    unsigned b1 = wbc[(kk + t4 + 4) * WB_STR + nb + gid];
                    mma8(acc[0][nt], a[0][0], a[0][1], a[0][2], a[0][3], b0, b1);
                    mma8(acc[1][nt], a[1][0], a[1][1], a[1][2], a[1][3], b0, b1);
                }
            }
            if (c < 15) {
                unsigned* wbn = ((c + 1) & 1) ? wbA : wb;
                #pragma unroll
                for (int i = 0; i < 8; ++i)
                    ((uint4*)wbn)[srow * (WB_STR / 4) + scol + 8 * i] = rg[i];
            }
            __syncthreads();
        }

        // epilogue: + b2 -> out
        #pragma unroll
        for (int mt = 0; mt < 2; ++mt) {
            int r0 = t0 + mw * 32 + mt * 16 + gid;
            #pragma unroll
            for (int nt = 0; nt < 8; ++nt) {
                int col = nw * 64 + nt * 8 + 2 * t4;
                float2 bb = *(const float2*)(b2 + col);
                float2 o0 = make_float2(acc[mt][nt][0] + bb.x, acc[mt][nt][1] + bb.y);
                float2 o1 = make_float2(acc[mt][nt][2] + bb.x, acc[mt][nt][3] + bb.y);
                *(float2*)(out + ((size_t)b * TT + r0) * DD + col)     = o0;
                *(float2*)(out + ((size_t)b * TT + r0 + 8) * DD + col) = o1;
            }
        }
    }
}

// ---------------- launch ----------------------------------------------------
extern "C" void kernel_launch(void* const* d_in, const int* in_sizes, int n_in,
                              void* d_out, int out_size) {
    const int*   byte_ids   = (const int*)d_in[0];
    const float* freq_bands = (const float*)d_in[1];
    const float* w1         = (const float*)d_in[2];
    const float* b1         = (const float*)d_in[3];
    const float* gamma      = (const float*)d_in[4];
    const float* beta       = (const float*)d_in[5];
    const float* w2         = (const float*)d_in[6];
    const float* b2         = (const float*)d_in[7];
    float* out = (float*)d_out;

    size_t smem_bytes = (size_t)SM_WORDS * sizeof(float);  // ~201 KB
    cudaFuncSetAttribute(k_main, cudaFuncAttributeMaxDynamicSharedMemorySize,
                         (int)smem_bytes);

    k_prep<<<(HH * DD + 255) / 256, 256>>>(w1, w2);
    k_all<<<BB, 1024>>>(byte_ids, freq_bands, w1, b1);
    k_main<<<dim3(TT / TBLK, BB), NTHR, smem_bytes>>>(b2, gamma, beta, out);
}

// round 9
// speedup vs baseline: 1.0614x; 1.0614x over previous
#include <cuda_runtime.h>
#include <math.h>

#define BB 32
#define TT 4096
#define DD 256
#define KK 128         // frequency count = D/2
#define HH 512         // hidden = 2*D
#define TBLK 64        // tokens per block in main kernel
#define NTHR 512       // 16 warps -> 4 warps/SMSP

// ---------------- scratch (global __device__, no allocation) ----------------
__device__ float2 g_tab[TT];        // (cos(2*pi*m/T), sin(2*pi*m/T))
__device__ float2 g_s0c0[BB * KK];  // (sin(phase0), cos(phase0))
__device__ float  g_base[BB * HH];  // mag @ w1[:128,:] + b1  (exact fp32 path)
__device__ unsigned g_w1t[KK * HH]; // tf32 bits of w1 rows 128..255
__device__ unsigned g_w2t[HH * DD]; // tf32 bits of w2

__device__ __forceinline__ unsigned f2tf32(float x) {
    unsigned r;
    asm("cvt.rna.tf32.f32 %0, %1;" : "=r"(r) : "f"(x));
    return r;
}

__device__ __forceinline__ void mma8(float* d,
                                     unsigned a0, unsigned a1, unsigned a2, unsigned a3,
                                     unsigned b0, unsigned b1) {
    asm volatile("mma.sync.aligned.m16n8k8.row.col.f32.tf32.tf32.f32 "
                 "{%0,%1,%2,%3}, {%4,%5,%6,%7}, {%8,%9}, {%0,%1,%2,%3};\n"
                 : "+f"(d[0]), "+f"(d[1]), "+f"(d[2]), "+f"(d[3])
                 : "r"(a0), "r"(a1), "r"(a2), "r"(a3), "r"(b0), "r"(b1));
}

// ---------------- kernel A: weights -> tf32 bits ----------------------------
__global__ void k_prep(const float* __restrict__ w1, const float* __restrict__ w2) {
    int i = blockIdx.x * blockDim.x + threadIdx.x;
    if (i < KK * HH) g_w1t[i] = f2tf32(w1[KK * HH + i]);   // rows 128..255
    if (i < HH * DD) g_w2t[i] = f2tf32(w2[i]);
}

// ---------------- kernel B: per-batch DFT + mag-fold (tab, dft, base) -------
__global__ void __launch_bounds__(1024, 1)
k_all(const int* __restrict__ byte_ids,
      const float* __restrict__ freq_bands,
      const float* __restrict__ w1,
      const float* __restrict__ b1) {
    __shared__ float  sig[TT];     // 16 KB
    __shared__ float2 stab[TT];    // 32 KB
    __shared__ float  mg[KK];      // mag * freq_bands

    int b = blockIdx.x;
    int tid = threadIdx.x;
    int w = tid >> 5, lane = tid & 31;

    #pragma unroll
    for (int q = 0; q < 4; ++q) {
        int m = tid + q * 1024;
        float s, c;
        sincospif((float)m * (1.0f / 2048.0f), &s, &c);
        stab[m] = make_float2(c, s);
        sig[m] = (float)byte_ids[b * TT + m] * (1.0f / 127.5f) - 1.0f;
    }
    __syncthreads();

    if (b == 0) {
        #pragma unroll
        for (int q = 0; q < 4; ++q) g_tab[tid + q * 1024] = stab[tid + q * 1024];
    }

    #pragma unroll 1
    for (int q = 0; q < 4; ++q) {
        int f = q * 32 + w;
        float re = 0.f, im = 0.f;
        #pragma unroll 4
        for (int t = lane; t < TT; t += 32) {
            int m = (f * t) & (TT - 1);
            float2 cs = stab[m];
            float s = sig[t];
            re += s * cs.x;
            im -= s * cs.y;
        }
        #pragma unroll
        for (int o = 16; o > 0; o >>= 1) {
            re += __shfl_xor_sync(0xffffffffu, re, o);
            im += __shfl_xor_sync(0xffffffffu, im, o);
        }
        if (lane == 0) {
            float mr = sqrtf(re * re + im * im);
            float s0, c0;
            if (mr > 0.f) { s0 = im / mr; c0 = re / mr; }
            else          { s0 = 0.f;    c0 = 1.f;    }
            mg[f] = mr * freq_bands[f];
            g_s0c0[b * KK + f] = make_float2(s0, c0);
        }
    }
    __syncthreads();

    if (tid < HH) {
        float acc = b1[tid];
        #pragma unroll 8
        for (int f = 0; f < KK; ++f) acc += mg[f] * w1[f * HH + tid];
        g_base[b * HH + tid] = acc;
    }
}

// ---------------- kernel C: fused feats->MMA1->LN->GELU->MMA2 ---------------
#define SA_STR 132
#define SG_STR 516
#define WB_STR 264
#define OFF_SA   0
#define OFF_SG   (TBLK * SA_STR)                 // 8448
#define OFF_WB   (OFF_SG + TBLK * SG_STR)        // 41472
#define OFF_BASE (OFF_WB + 32 * WB_STR)          // 49920
#define OFF_GAM  (OFF_BASE + HH)
#define OFF_BET  (OFF_GAM + HH)
#define SM_WORDS (OFF_BET + HH)                  // 51456 words = 205824 B

__global__ void __launch_bounds__(NTHR, 1)
k_main(const float* __restrict__ b2,
       const float* __restrict__ gamma,
       const float* __restrict__ beta,
       float* __restrict__ out) {
    extern __shared__ float smem[];
    unsigned* sa   = (unsigned*)smem + OFF_SA;
    float*    sGf  = smem + OFF_SG;
    unsigned* sGu  = (unsigned*)smem + OFF_SG;
    unsigned* wb   = (unsigned*)smem + OFF_WB;
    unsigned* wbA  = (unsigned*)smem + OFF_SA;   // GEMM2 second weight buffer
    float*    sbase = smem + OFF_BASE;
    float*    sgam  = smem + OFF_GAM;
    float*    sbet  = smem + OFF_BET;

    int tid  = threadIdx.x;
    int lane = tid & 31, warp = tid >> 5;        // 16 warps
    int b = blockIdx.y, t0 = blockIdx.x * TBLK;
    int mw = warp & 3, nw = warp >> 2;           // warp tile: 16 rows x 64 cols
    int gid = lane >> 2, t4 = lane & 3;
    int rb = mw * 16;

    // ---- feats: a[t][f] = sin(phase0 + 2*pi*f*(t0+t)/T), stored as tf32 ----
    for (int e = tid; e < TBLK * KK; e += NTHR) {
        int t = e >> 7, f = e & (KK - 1);
        int m = (f * (t0 + t)) & (TT - 1);
        float2 cs = g_tab[m];
        float2 sc = g_s0c0[b * KK + f];
        sa[t * SA_STR + f] = f2tf32(sc.x * cs.x + sc.y * cs.y);
    }
    if (tid < HH) {
        sbase[tid] = g_base[b * HH + tid];
        sgam[tid]  = gamma[tid];
        sbet[tid]  = beta[tid];
    }
    __syncthreads();

    // =========================== GEMM1 =====================================
    // h[64][512] = a[64][128] @ w1s[128][512] + base, two N-passes of 256
    {
        int srow = tid >> 5, scol = tid & 31;    // stage: 16 rows x 256 cols
        for (int p = 0; p < 2; ++p) {
            int n0 = p * 256;
            float acc[8][4];
            #pragma unroll
            for (int nt = 0; nt < 8; ++nt)
                #pragma unroll
                for (int q = 0; q < 4; ++q) acc[nt][q] = 0.f;

            uint4 rg[2];
            const uint4* wsrc = (const uint4*)g_w1t;
            #pragma unroll
            for (int i = 0; i < 2; ++i)
                rg[i] = wsrc[srow * (HH / 4) + (n0 >> 2) + scol + 32 * i];
            #pragma unroll
            for (int i = 0; i < 2; ++i)
                ((uint4*)wb)[srow * (WB_STR / 4) + scol + 32 * i] = rg[i];
            __syncthreads();

            for (int c = 0; c < 8; ++c) {
                int pb = c & 1;
                if (c < 7) {
                    #pragma unroll
                    for (int i = 0; i < 2; ++i)
                        rg[i] = wsrc[((c + 1) * 16 + srow) * (HH / 4) + (n0 >> 2) + scol + 32 * i];
                }
                const unsigned* wbc = wb + pb * 16 * WB_STR;
                #pragma unroll
                for (int kk = 0; kk < 16; kk += 8) {
                    int kg = c * 16 + kk;
                    unsigned a0 = sa[(rb + gid)     * SA_STR + kg + t4];
                    unsigned a1 = sa[(rb + gid + 8) * SA_STR + kg + t4];
                    unsigned a2 = sa[(rb + gid)     * SA_STR + kg + t4 + 4];
                    unsigned a3 = sa[(rb + gid + 8) * SA_STR + kg + t4 + 4];
                    #pragma unroll
                    for (int nt = 0; nt < 8; ++nt) {
                        int nb = nw * 64 + nt * 8;
                        unsigned b0 = wbc[(kk + t4)     * WB_STR + nb + gid];
                        unsigned b1 = wbc[(kk + t4 + 4) * WB_STR + nb + gid];
                        mma8(acc[nt], a0, a1, a2, a3, b0, b1);
                    }
                }
                if (c < 7) {
                    int pb2 = (c + 1) & 1;
                    #pragma unroll
                    for (int i = 0; i < 2; ++i)
                        ((uint4*)wb)[pb2 * 16 * (WB_STR / 4) + srow * (WB_STR / 4) + scol + 32 * i] = rg[i];
                }
                __syncthreads();
            }
            // epilogue: h = acc + base -> sG (fp32)
            int r0 = rb + gid;
            #pragma unroll
            for (int nt = 0; nt < 8; ++nt) {
                int col = n0 + nw * 64 + nt * 8 + 2 * t4;
                float2 v0 = make_float2(acc[nt][0] + sbase[col],
                                        acc[nt][1] + sbase[col + 1]);
                float2 v1 = make_float2(acc[nt][2] + sbase[col],
                                        acc[nt][3] + sbase[col + 1]);
                *(float2*)(sGf + r0 * SG_STR + col)       = v0;
                *(float2*)(sGf + (r0 + 8) * SG_STR + col) = v1;
            }
        }
    }
    __syncthreads();

    // ---- LayerNorm + exact GELU (erf form); store back as tf32 bits ----
    {
        int row = tid >> 3, part = tid & 7;      // 8 threads per row
        float* hr = sGf + row * SG_STR;
        float sum = 0.f, sq = 0.f;
        #pragma unroll 8
        for (int i = 0; i < 64; ++i) {
            float v = hr[part + 8 * i];          // interleaved: <=2-way conflicts
            sum += v; sq += v * v;
        }
        #pragma unroll
        for (int o = 1; o < 8; o <<= 1) {
            sum += __shfl_xor_sync(0xffffffffu, sum, o);
            sq  += __shfl_xor_sync(0xffffffffu, sq,  o);
        }
        float mu  = sum * (1.0f / 512.0f);
        float var = sq * (1.0f / 512.0f) - mu * mu;
        float rs  = rsqrtf(var + 1e-5f);
        unsigned* hu = (unsigned*)hr;
        #pragma unroll 8
        for (int i = 0; i < 64; ++i) {
            int j = part + 8 * i;
            float v = (hr[j] - mu) * rs * sgam[j] + sbet[j];
            float g = 0.5f * v * (1.0f + erff(v * 0.70710678118654752f));
            hu[j] = f2tf32(g);   // exact GELU via erf
        }
    }
    __syncthreads();

    // =========================== GEMM2 =====================================
    // out[64][256] = g[64][512] @ w2[512][256] + b2, single N-pass
    {
        float acc[8][4];
        #pragma unroll
        for (int nt = 0; nt < 8; ++nt)
            #pragma unroll
            for (int q = 0; q < 4; ++q) acc[nt][q] = 0.f;

        int srow = tid >> 4, scol = tid & 15;    // stage: 32 rows x 256 cols
        uint4 rg[4];
        const uint4* wsrc = (const uint4*)g_w2t;
        #pragma unroll
        for (int i = 0; i < 4; ++i)
            rg[i] = wsrc[srow * (DD / 4) + scol + 16 * i];
        #pragma unroll
        for (int i = 0; i < 4; ++i)
            ((uint4*)wb)[srow * (WB_STR / 4) + scol + 16 * i] = rg[i];
        __syncthreads();

        for (int c = 0; c < 16; ++c) {
            const unsigned* wbc = (c & 1) ? wbA : wb;
            if (c < 15) {
                #pragma unroll
                for (int i = 0; i < 4; ++i)
                    rg[i] = wsrc[((c + 1) * 32 + srow) * (DD / 4) + scol + 16 * i];
            }
            #pragma unroll
            for (int kk = 0; kk < 32; kk += 8) {
                int kg = c * 32 + kk;
                unsigned a0 = sGu[(rb + gid)     * SG_STR + kg + t4];
                unsigned a1 = sGu[(rb + gid + 8) * SG_STR + kg + t4];
                unsigned a2 = sGu[(rb + gid)     * SG_STR + kg + t4 + 4];
                unsigned a3 = sGu[(rb + gid + 8) * SG_STR + kg + t4 + 4];
                #pragma unroll
                for (int nt = 0; nt < 8; ++nt) {
                    int nb = nw * 64 + nt * 8;
                    unsigned b0 = wbc[(kk + t4)     * WB_STR + nb + gid];
                    unsigned b1 = wbc[(kk + t4 + 4) * WB_STR + nb + gid];
                    mma8(acc[nt], a0, a1, a2, a3, b0, b1);
                }
            }
            if (c < 15) {
                unsigned* wbn = ((c + 1) & 1) ? wbA : wb;
                #pragma unroll
                for (int i = 0; i < 4; ++i)
                    ((uint4*)wbn)[srow * (WB_STR / 4) + scol + 16 * i] = rg[i];
            }
            __syncthreads();
        }

        // epilogue: + b2 -> out
        int r0 = t0 + rb + gid;
        #pragma unroll
        for (int nt = 0; nt < 8; ++nt) {
            int col = nw * 64 + nt * 8 + 2 * t4;
            float2 bb = *(const float2*)(b2 + col);
            float2 o0 = make_float2(acc[nt][0] + bb.x, acc[nt][1] + bb.y);
            float2 o1 = make_float2(acc[nt][2] + bb.x, acc[nt][3] + bb.y);
            *(float2*)(out + ((size_t)b * TT + r0) * DD + col)     = o0;
            *(float2*)(out + ((size_t)b * TT + r0 + 8) * DD + col) = o1;
        }
    }
}

// ---------------- launch ----------------------------------------------------
extern "C" void kernel_launch(void* const* d_in, const int* in_sizes, int n_in,
                              void* d_out, int out_size) {
    const int*   byte_ids   = (const int*)d_in[0];
    const float* freq_bands = (const float*)d_in[1];
    const float* w1         = (const float*)d_in[2];
    const float* b1         = (const float*)d_in[3];
    const float* gamma      = (const float*)d_in[4];
    const float* beta       = (const float*)d_in[5];
    const float* w2         = (const float*)d_in[6];
    const float* b2         = (const float*)d_in[7];
    float* out = (float*)d_out;

    size_t smem_bytes = (size_t)SM_WORDS * sizeof(float);  // ~201 KB
    cudaFuncSetAttribute(k_main, cudaFuncAttributeMaxDynamicSharedMemorySize,
                         (int)smem_bytes);

    k_prep<<<(HH * DD + 255) / 256, 256>>>(w1, w2);
    k_all<<<BB, 1024>>>(byte_ids, freq_bands, w1, b1);
    k_main<<<dim3(TT / TBLK, BB), NTHR, smem_bytes>>>(b2, gamma, beta, out);
}

// round 11
// speedup vs baseline: 1.5033x; 1.4164x over previous
#include <cuda_runtime.h>
#include <cuda_fp16.h>
#include <math.h>

#define BB 32
#define TT 4096
#define DD 256
#define KK 128         // frequency count = D/2
#define HH 512         // hidden = 2*D
#define TBLK 64        // tokens per block in main kernel
#define NTHR 512       // 16 warps -> 4 warps/SMSP

// ---------------- scratch (global __device__, no allocation) ----------------
__device__ float2   g_tab[TT];        // (cos, sin)
__device__ float2   g_s0c0[BB * KK];  // (sin(phase0), cos(phase0))
__device__ float    g_base[BB * HH];  // mag @ w1[:128,:] + b1 (exact fp32)
__device__ unsigned g_w1h[(KK / 2) * HH];  // half2-packed w1 rows 128..255: [kw][n]
__device__ unsigned g_w2h[(HH / 2) * DD];  // half2-packed w2: [kw][n]

__device__ __forceinline__ unsigned packh2(float lo, float hi) {
    __half2 h = __floats2half2_rn(lo, hi);
    return *(unsigned*)&h;
}

__device__ __forceinline__ void mma16(float* d,
                                      unsigned a0, unsigned a1, unsigned a2, unsigned a3,
                                      unsigned b0, unsigned b1) {
    asm volatile("mma.sync.aligned.m16n8k16.row.col.f32.f16.f16.f32 "
                 "{%0,%1,%2,%3}, {%4,%5,%6,%7}, {%8,%9}, {%0,%1,%2,%3};\n"
                 : "+f"(d[0]), "+f"(d[1]), "+f"(d[2]), "+f"(d[3])
                 : "r"(a0), "r"(a1), "r"(a2), "r"(a3), "r"(b0), "r"(b1));
}

// ---------------- kernel A: weights -> packed half2 -------------------------
__global__ void k_prep(const float* __restrict__ w1, const float* __restrict__ w2) {
    int i = blockIdx.x * blockDim.x + threadIdx.x;
    if (i < (KK / 2) * HH) {
        int kw = i / HH, j = i % HH;
        g_w1h[i] = packh2(w1[(KK + 2 * kw) * HH + j], w1[(KK + 2 * kw + 1) * HH + j]);
    }
    if (i < (HH / 2) * DD) {
        int kw = i / DD, j = i % DD;
        g_w2h[i] = packh2(w2[(2 * kw) * DD + j], w2[(2 * kw + 1) * DD + j]);
    }
}

// ---------------- kernel B: per-batch DFT + mag-fold ------------------------
__global__ void __launch_bounds__(1024, 1)
k_all(const int* __restrict__ byte_ids,
      const float* __restrict__ freq_bands,
      const float* __restrict__ w1,
      const float* __restrict__ b1) {
    __shared__ float  sig[TT];
    __shared__ float2 stab[TT];
    __shared__ float  mg[KK];

    int b = blockIdx.x;
    int tid = threadIdx.x;
    int w = tid >> 5, lane = tid & 31;

    #pragma unroll
    for (int q = 0; q < 4; ++q) {
        int m = tid + q * 1024;
        float s, c;
        sincospif((float)m * (1.0f / 2048.0f), &s, &c);
        stab[m] = make_float2(c, s);
        sig[m] = (float)byte_ids[b * TT + m] * (1.0f / 127.5f) - 1.0f;
    }
    __syncthreads();

    if (b == 0) {
        #pragma unroll
        for (int q = 0; q < 4; ++q) g_tab[tid + q * 1024] = stab[tid + q * 1024];
    }

    #pragma unroll 1
    for (int q = 0; q < 4; ++q) {
        int f = q * 32 + w;
        float re = 0.f, im = 0.f;
        #pragma unroll 4
        for (int t = lane; t < TT; t += 32) {
            int m = (f * t) & (TT - 1);
            float2 cs = stab[m];
            float s = sig[t];
            re += s * cs.x;
            im -= s * cs.y;
        }
        #pragma unroll
        for (int o = 16; o > 0; o >>= 1) {
            re += __shfl_xor_sync(0xffffffffu, re, o);
            im += __shfl_xor_sync(0xffffffffu, im, o);
        }
        if (lane == 0) {
            float mr = sqrtf(re * re + im * im);
            float s0, c0;
            if (mr > 0.f) { s0 = im / mr; c0 = re / mr; }
            else          { s0 = 0.f;    c0 = 1.f;    }
            mg[f] = mr * freq_bands[f];
            g_s0c0[b * KK + f] = make_float2(s0, c0);
        }
    }
    __syncthreads();

    if (tid < HH) {
        float acc = b1[tid];
        #pragma unroll 8
        for (int f = 0; f < KK; ++f) acc += mg[f] * w1[f * HH + tid];
        g_base[b * HH + tid] = acc;
    }
}

// ---------------- kernel C: fused feats->MMA1->LN->GELU->MMA2 (fp16) --------
// smem word layout:
//   sa   [64][68]   half2-packed sin feats (k-pairs)          4352 w
//   sG   [64][516]  fp32 h; packed half2 g at even slots      33024 w
//   wb   [64][264]  half2 weight staging (GEMM2: 2x32-row)    16896 w
//   sbase/sgam/sbet [512] each                                 1536 w
#define SA_STR 68
#define SG_STR 516
#define WB_STR 264
#define OFF_SA   0
#define OFF_SG   (TBLK * SA_STR)                 // 4352
#define OFF_WB   (OFF_SG + TBLK * SG_STR)        // 37376
#define OFF_BASE (OFF_WB + 64 * WB_STR)          // 54272
#define OFF_GAM  (OFF_BASE + HH)
#define OFF_BET  (OFF_GAM + HH)
#define SM_WORDS (OFF_BET + HH)                  // 55808 words = 223232 B

__global__ void __launch_bounds__(NTHR, 1)
k_main(const float* __restrict__ b2,
       const float* __restrict__ gamma,
       const float* __restrict__ beta,
       float* __restrict__ out) {
    extern __shared__ float smem[];
    unsigned* sa   = (unsigned*)smem + OFF_SA;
    float*    sGf  = smem + OFF_SG;
    unsigned* sGu  = (unsigned*)smem + OFF_SG;
    unsigned* wb   = (unsigned*)smem + OFF_WB;
    float*    sbase = smem + OFF_BASE;
    float*    sgam  = smem + OFF_GAM;
    float*    sbet  = smem + OFF_BET;

    int tid  = threadIdx.x;
    int lane = tid & 31, warp = tid >> 5;        // 16 warps
    int b = blockIdx.y, t0 = blockIdx.x * TBLK;
    int mw = warp & 3, nw = warp >> 2;           // warp tile: 16 rows x 64 cols
    int gid = lane >> 2, t4 = lane & 3;
    int rb = mw * 16;

    // ---- feats: packed half2 pairs sin(f=2kw), sin(f=2kw+1) ----
    for (int e = tid; e < TBLK * (KK / 2); e += NTHR) {
        int t = e >> 6, kw = e & 63;
        int f0 = 2 * kw;
        int m0 = (f0 * (t0 + t)) & (TT - 1);
        int m1 = ((f0 + 1) * (t0 + t)) & (TT - 1);
        float2 cs0 = g_tab[m0], cs1 = g_tab[m1];
        float2 sc0 = g_s0c0[b * KK + f0], sc1 = g_s0c0[b * KK + f0 + 1];
        float v0 = sc0.x * cs0.x + sc0.y * cs0.y;
        float v1 = sc1.x * cs1.x + sc1.y * cs1.y;
        sa[t * SA_STR + kw] = packh2(v0, v1);
    }
    if (tid < HH) {
        sbase[tid] = g_base[b * HH + tid];
        sgam[tid]  = gamma[tid];
        sbet[tid]  = beta[tid];
    }
    __syncthreads();

    // =========================== GEMM1 =====================================
    // h[64][512] = a[64][128] @ w1s[128][512] + base, two N-passes of 256.
    // All 64 k-words of B for one pass fit in wb -> single stage, no dbuf.
    for (int p = 0; p < 2; ++p) {
        int n0 = p * 256;
        // stage B: 64 rows x 64 uint4 (256 words)
        #pragma unroll
        for (int i = 0; i < 8; ++i) {
            int u = tid + NTHR * i;          // 0..4095
            int row = u >> 6, col = u & 63;
            ((uint4*)wb)[row * (WB_STR / 4) + col] =
                ((const uint4*)g_w1h)[row * (HH / 4) + (n0 >> 2) + col];
        }
        __syncthreads();

        float acc[8][4];
        #pragma unroll
        for (int nt = 0; nt < 8; ++nt)
            #pragma unroll
            for (int q = 0; q < 4; ++q) acc[nt][q] = 0.f;

        #pragma unroll
        for (int s = 0; s < 8; ++s) {        // 8 x k16
            int kw0 = s * 8;
            unsigned a0 = sa[(rb + gid)     * SA_STR + kw0 + t4];
            unsigned a1 = sa[(rb + gid + 8) * SA_STR + kw0 + t4];
            unsigned a2 = sa[(rb + gid)     * SA_STR + kw0 + t4 + 4];
            unsigned a3 = sa[(rb + gid + 8) * SA_STR + kw0 + t4 + 4];
            #pragma unroll
            for (int nt = 0; nt < 8; ++nt) {
                int nb = nw * 64 + nt * 8;
                unsigned b0 = wb[(kw0 + t4)     * WB_STR + nb + gid];
                unsigned b1 = wb[(kw0 + t4 + 4) * WB_STR + nb + gid];
                mma16(acc[nt], a0, a1, a2, a3, b0, b1);
            }
        }

        // epilogue: h = acc + base -> sG (fp32)
        int r0 = rb + gid;
        #pragma unroll
        for (int nt = 0; nt < 8; ++nt) {
            int col = n0 + nw * 64 + nt * 8 + 2 * t4;
            float2 v0 = make_float2(acc[nt][0] + sbase[col], acc[nt][1] + sbase[col + 1]);
            float2 v1 = make_float2(acc[nt][2] + sbase[col], acc[nt][3] + sbase[col + 1]);
            *(float2*)(sGf + r0 * SG_STR + col)       = v0;
            *(float2*)(sGf + (r0 + 8) * SG_STR + col) = v1;
        }
        __syncthreads();
    }

    // ---- LayerNorm + exact GELU (erf); write packed half2 at even slots ----
    {
        int row = tid >> 3, part = tid & 7;      // 8 threads per row, 32 pairs each
        float* hr = sGf + row * SG_STR;
        unsigned* hu = (unsigned*)hr;
        float sum = 0.f, sq = 0.f;
        #pragma unroll 8
        for (int i = 0; i < 32; ++i) {
            int kw = part + 8 * i;
            float v0 = hr[2 * kw], v1 = hr[2 * kw + 1];
            sum += v0 + v1; sq += v0 * v0 + v1 * v1;
        }
        #pragma unroll
        for (int o = 1; o < 8; o <<= 1) {
            sum += __shfl_xor_sync(0xffffffffu, sum, o);
            sq  += __shfl_xor_sync(0xffffffffu, sq,  o);
        }
        float mu  = sum * (1.0f / 512.0f);
        float var = sq * (1.0f / 512.0f) - mu * mu;
        float rs  = rsqrtf(var + 1e-5f);
        #pragma unroll 4
        for (int i = 0; i < 32; ++i) {
            int kw = part + 8 * i;
            int j0 = 2 * kw;
            float v0 = (hr[j0]     - mu) * rs * sgam[j0]     + sbet[j0];
            float v1 = (hr[j0 + 1] - mu) * rs * sgam[j0 + 1] + sbet[j0 + 1];
            float g0 = 0.5f * v0 * (1.0f + erff(v0 * 0.70710678118654752f));
            float g1 = 0.5f * v1 * (1.0f + erff(v1 * 0.70710678118654752f));
            hu[j0] = packh2(g0, g1);   // packed at even slot; odd slot now dead
        }
    }
    __syncthreads();

    // =========================== GEMM2 =====================================
    // out[64][256] = g[64][512] @ w2[512][256] + b2
    // K = 256 k-words; 8 chunks of 32 k-words, double-buffered in wb.
    {
        float acc[8][4];
        #pragma unroll
        for (int nt = 0; nt < 8; ++nt)
            #pragma unroll
            for (int q = 0; q < 4; ++q) acc[nt][q] = 0.f;

        uint4 rg[4];
        // prologue: chunk 0 -> buf0
        #pragma unroll
        for (int i = 0; i < 4; ++i) {
            int u = tid + NTHR * i;          // 0..2047
            int row = u >> 6, col = u & 63;
            rg[i] = ((const uint4*)g_w2h)[row * (DD / 4) + col];
        }
        #pragma unroll
        for (int i = 0; i < 4; ++i) {
            int u = tid + NTHR * i;
            int row = u >> 6, col = u & 63;
            ((uint4*)wb)[row * (WB_STR / 4) + col] = rg[i];
        }
        __syncthreads();

        for (int c = 0; c < 8; ++c) {
            const unsigned* wbc = wb + (c & 1) * 32 * WB_STR;
            if (c < 7) {
                #pragma unroll
                for (int i = 0; i < 4; ++i) {
                    int u = tid + NTHR * i;
                    int row = u >> 6, col = u & 63;
                    rg[i] = ((const uint4*)g_w2h)[((c + 1) * 32 + row) * (DD / 4) + col];
                }
            }
            #pragma unroll
            for (int s = 0; s < 4; ++s) {    // 4 x k16 per chunk
                int kwl = s * 8;
                int kg = c * 32 + kwl;
                unsigned a0 = sGu[(rb + gid)     * SG_STR + 2 * (kg + t4)];
                unsigned a1 = sGu[(rb + gid + 8) * SG_STR + 2 * (kg + t4)];
                unsigned a2 = sGu[(rb + gid)     * SG_STR + 2 * (kg + t4 + 4)];
                unsigned a3 = sGu[(rb + gid + 8) * SG_STR + 2 * (kg + t4 + 4)];
                #pragma unroll
                for (int nt = 0; nt < 8; ++nt) {
                    int nb = nw * 64 + nt * 8;
                    unsigned b0 = wbc[(kwl + t4)     * WB_STR + nb + gid];
                    unsigned b1 = wbc[(kwl + t4 + 4) * WB_STR + nb + gid];
                    mma16(acc[nt], a0, a1, a2, a3, b0, b1);
                }
            }
            if (c < 7) {
                unsigned* wbn = wb + ((c + 1) & 1) * 32 * WB_STR;
                #pragma unroll
                for (int i = 0; i < 4; ++i) {
                    int u = tid + NTHR * i;
                    int row = u >> 6, col = u & 63;
                    ((uint4*)wbn)[row * (WB_STR / 4) + col] = rg[i];
                }
            }
            __syncthreads();
        }

        // epilogue: + b2 -> out
        int r0 = t0 + rb + gid;
        #pragma unroll
        for (int nt = 0; nt < 8; ++nt) {
            int col = nw * 64 + nt * 8 + 2 * t4;
            float2 bb = *(const float2*)(b2 + col);
            float2 o0 = make_float2(acc[nt][0] + bb.x, acc[nt][1] + bb.y);
            float2 o1 = make_float2(acc[nt][2] + bb.x, acc[nt][3] + bb.y);
            *(float2*)(out + ((size_t)b * TT + r0) * DD + col)     = o0;
            *(float2*)(out + ((size_t)b * TT + r0 + 8) * DD + col) = o1;
        }
    }
}

// ---------------- launch ----------------------------------------------------
extern "C" void kernel_launch(void* const* d_in, const int* in_sizes, int n_in,
                              void* d_out, int out_size) {
    const int*   byte_ids   = (const int*)d_in[0];
    const float* freq_bands = (const float*)d_in[1];
    const float* w1         = (const float*)d_in[2];
    const float* b1         = (const float*)d_in[3];
    const float* gamma      = (const float*)d_in[4];
    const float* beta       = (const float*)d_in[5];
    const float* w2         = (const float*)d_in[6];
    const float* b2         = (const float*)d_in[7];
    float* out = (float*)d_out;

    size_t smem_bytes = (size_t)SM_WORDS * sizeof(float);  // ~218 KB
    cudaFuncSetAttribute(k_main, cudaFuncAttributeMaxDynamicSharedMemorySize,
                         (int)smem_bytes);

    k_prep<<<((HH / 2) * DD + 255) / 256, 256>>>(w1, w2);
    k_all<<<BB, 1024>>>(byte_ids, freq_bands, w1, b1);
    k_main<<<dim3(TT / TBLK, BB), NTHR, smem_bytes>>>(b2, gamma, beta, out);
}